// round 14
// baseline (speedup 1.0000x reference)
#include <cuda_runtime.h>
#include <cuda_bf16.h>
#include <stdint.h>

#define TT 128
#define MAXB 4096

// ---------------- scratch ----------------
__device__ uint32_t g_h1b[(size_t)MAXB * TT * 32];  // layer1 bidi out, bf16x2 [B][T][32]
__device__ float    g_h2[MAXB * 32];                // layer2 concat [B][32]

// ---------------- helpers ----------------
__device__ __forceinline__ uint32_t bf2(float lo, float hi) {
    uint32_t r;
    asm("cvt.rn.bf16x2.f32 %0, %1, %2;" : "=r"(r) : "f"(hi), "f"(lo));
    return r;
}
__device__ __forceinline__ float tanhx(float x) {
    float y; asm("tanh.approx.f32 %0, %1;" : "=f"(y) : "f"(x)); return y;
}
__device__ __forceinline__ float sigx(float x) {
    return fmaf(tanhx(x * 0.5f), 0.5f, 0.5f);
}
__device__ __forceinline__ void mma_bf16(float* d, const uint4& a, uint32_t b0, uint32_t b1) {
    asm volatile(
        "mma.sync.aligned.m16n8k16.row.col.f32.bf16.bf16.f32 "
        "{%0,%1,%2,%3},{%4,%5,%6,%7},{%8,%9},{%0,%1,%2,%3};"
        : "+f"(d[0]), "+f"(d[1]), "+f"(d[2]), "+f"(d[3])
        : "r"(a.x), "r"(a.y), "r"(a.z), "r"(a.w), "r"(b0), "r"(b1));
}

// stage x (lstm1): redistribute prefetched v0/v1 via shfl, one STS.128
#define L1_STAGE(DST) do { \
    const uint32_t pa0 = bf2(v0.x, v0.y), pa1 = bf2(v0.z, v0.w); \
    const uint32_t pb0 = bf2(v1.x, v1.y), pb1 = bf2(v1.z, v1.w); \
    const uint32_t a0l = __shfl_sync(0xffffffffu, pa0, srcLo); \
    const uint32_t a1l = __shfl_sync(0xffffffffu, pa1, srcLo); \
    const uint32_t b0l = __shfl_sync(0xffffffffu, pb0, srcLo); \
    const uint32_t b1l = __shfl_sync(0xffffffffu, pb1, srcLo); \
    const uint32_t a0h = __shfl_sync(0xffffffffu, pa0, srcHi); \
    const uint32_t a1h = __shfl_sync(0xffffffffu, pa1, srcHi); \
    const uint32_t b0h = __shfl_sync(0xffffffffu, pb0, srcHi); \
    const uint32_t b1h = __shfl_sync(0xffffffffu, pb1, srcHi); \
    *(uint4*)((DST) + q * 128 + l * 4) = make_uint4( \
        oddT ? a1l : a0l, oddT ? b1l : b0l, \
        oddT ? a1h : a0h, oddT ? b1h : b0h); \
} while (0)

// ================= layer 1: H=32, KIN=64, K=96 (KC=6), seq out (bf16) ========
// R11 skeleton + RECURRENCE SPLIT: accumulator d enters step t holding
// bias + x_t@W (kc0-3, precomputed last step). Post-barrier critical path is
// only the 2-kc h-MMA + activations + h feedback; the 16 x-part MMAs for
// t+1, x staging and hout flush run in its shadow. One __syncthreads/step.
__global__ void __launch_bounds__(128) lstm1_mma(
    const float* __restrict__ in,
    const float* __restrict__ Wf, const float* __restrict__ Uf, const float* __restrict__ bf_,
    const float* __restrict__ Wb, const float* __restrict__ Ub, const float* __restrict__ bb)
{
    __shared__ uint32_t Bsm[6 * 16 * 32 * 2];               // 24KB (init only)
    __shared__ __align__(16) uint32_t Asm[2 * 6 * 128];     // 6KB: [buf][kc][128]
    __shared__ __align__(16) uint32_t houtS[2 * 288];       // 2.25KB
    __shared__ float biasS[128];

    const int dir = blockIdx.y;
    const float* W    = dir ? Wb : Wf;
    const float* U    = dir ? Ub : Uf;
    const float* bias = dir ? bb : bf_;

    const int tid = threadIdx.x;
    const int q   = tid >> 5;
    const int l   = tid & 31;
    const int gid = l >> 2;
    const int tig = l & 3;

    for (int idx = tid; idx < 6 * 16 * 32 * 2; idx += 128) {
        const int which = idx & 1;
        const int lane  = (idx >> 1) & 31;
        const int nt    = (idx >> 6) & 15;
        const int kc    = idx >> 10;
        const int k = kc * 16 + which * 8 + 2 * (lane & 3);
        const int n = nt * 8 + (lane >> 2);
        const float v0w = (k     < 64) ? W[k * 128 + n]       : U[(k - 64) * 128 + n];
        const float v1w = (k + 1 < 64) ? W[(k + 1) * 128 + n] : U[(k - 63) * 128 + n];
        Bsm[idx] = bf2(v0w, v1w);
    }
    if (tid < 128) biasS[tid] = bias[tid];
    // zero h region of buffer 0 (kc 4,5)
    for (int idx = tid; idx < 256; idx += 128) Asm[512 + idx] = 0;
    __syncthreads();

    uint32_t Br[6][4][2];
    #pragma unroll
    for (int kc = 0; kc < 6; kc++)
        #pragma unroll
        for (int g = 0; g < 4; g++) {
            const int base = ((kc * 16 + g * 4 + q) * 32 + l) * 2;
            Br[kc][g][0] = Bsm[base];
            Br[kc][g][1] = Bsm[base + 1];
        }

    float2 bz[4];
    #pragma unroll
    for (int g = 0; g < 4; g++) {
        const int col = g * 32 + q * 8 + 2 * tig;
        bz[g] = make_float2(biasS[col], biasS[col + 1]);
    }

    const int ws = blockIdx.x * 16;
    const float* xL0 = in + (size_t)(ws + gid) * TT * 64 + q * 16 + 4 * tig;
    const float* xL1 = xL0 + (size_t)8 * TT * 64;

    const int srcLo = (l & ~3) | (tig >> 1);
    const int srcHi = srcLo + 2;
    const bool oddT = (tig & 1) != 0;

    const int sF  = tid >> 3;
    const int ocF = tid & 7;

    float cc[4] = {0.f, 0.f, 0.f, 0.f};
    float d[4][4];   // loop-carried: bias + x_t@W entering each step
    float4 v0, v1;

    // ---- prologue: x(0)->buf0, x(1)->buf1, prefetch x(2); d = bias + x0@W ----
    {
        const int tt0 = dir ? TT - 1 : 0;
        v0 = *(const float4*)(xL0 + (size_t)tt0 * 64);
        v1 = *(const float4*)(xL1 + (size_t)tt0 * 64);
        L1_STAGE(Asm);
    }
    __syncthreads();
    #pragma unroll
    for (int g = 0; g < 4; g++) {
        d[g][0] = bz[g].x; d[g][1] = bz[g].y;
        d[g][2] = bz[g].x; d[g][3] = bz[g].y;
    }
    #pragma unroll
    for (int kc = 0; kc < 4; kc++) {
        const uint4 a = *((const uint4*)Asm + kc * 32 + l);
        #pragma unroll
        for (int g = 0; g < 4; g++)
            mma_bf16(d[g], a, Br[kc][g][0], Br[kc][g][1]);
    }
    {
        const int tt1 = dir ? TT - 2 : 1;
        v0 = *(const float4*)(xL0 + (size_t)tt1 * 64);
        v1 = *(const float4*)(xL1 + (size_t)tt1 * 64);
        L1_STAGE(Asm + 768);
        const int tt2 = dir ? TT - 3 : 2;
        v0 = *(const float4*)(xL0 + (size_t)tt2 * 64);
        v1 = *(const float4*)(xL1 + (size_t)tt2 * 64);
    }
    __syncthreads();

    for (int t = 0; t < TT; t++) {
        const int tt = dir ? TT - 1 - t : t;
        const uint32_t* Acur = Asm + (t & 1) * 768;
        uint32_t*       Anxt = Asm + ((t + 1) & 1) * 768;

        // ---- critical path: h-part MMA (kc4,5) into carried d ----
        #pragma unroll
        for (int kc = 4; kc < 6; kc++) {
            const uint4 a = *((const uint4*)Acur + kc * 32 + l);
            #pragma unroll
            for (int g = 0; g < 4; g++)
                mma_bf16(d[g], a, Br[kc][g][0], Br[kc][g][1]);
        }

        // shadow work 1: flush hout(t-1)
        if (t > 0) {
            const int tprev = dir ? tt + 1 : tt - 1;
            const uint2 hv = *(const uint2*)&houtS[((t - 1) & 1) * 288 + sF * 18 + ocF * 2];
            *(uint2*)&g_h1b[((size_t)(ws + sF) * TT + tprev) * 32 + dir * 16 + ocF * 2] = hv;
        }

        // ---- activations -> h(t) -> feedback + hout ----
        uint32_t hp[2];
        #pragma unroll
        for (int rh = 0; rh < 2; rh++) {
            float h0, h1;
            {
                const int p = rh * 2;
                const float ig = sigx(d[0][p]);
                const float fg = sigx(d[1][p]);
                const float gg = tanhx(d[2][p]);
                const float og = sigx(d[3][p]);
                const float c  = fg * cc[p] + ig * gg;
                h0 = og * tanhx(c); cc[p] = c;
            }
            {
                const int p = rh * 2 + 1;
                const float ig = sigx(d[0][p]);
                const float fg = sigx(d[1][p]);
                const float gg = tanhx(d[2][p]);
                const float og = sigx(d[3][p]);
                const float c  = fg * cc[p] + ig * gg;
                h1 = og * tanhx(c); cc[p] = c;
            }
            hp[rh] = bf2(h0, h1);
            houtS[(t & 1) * 288 + (gid + 8 * rh) * 18 + q * 4 + tig] = hp[rh];
        }
        *(uint2*)(Anxt + (4 + (q >> 1)) * 128 + l * 4 + (q & 1) * 2)
            = make_uint2(hp[0], hp[1]);

        // shadow work 2: pre-accumulate bias + x(t+1)@W for next step
        if (t + 1 < TT) {
            #pragma unroll
            for (int g = 0; g < 4; g++) {
                d[g][0] = bz[g].x; d[g][1] = bz[g].y;
                d[g][2] = bz[g].x; d[g][3] = bz[g].y;
            }
            #pragma unroll
            for (int kc = 0; kc < 4; kc++) {
                const uint4 a = *((const uint4*)Anxt + kc * 32 + l);
                #pragma unroll
                for (int g = 0; g < 4; g++)
                    mma_bf16(d[g], a, Br[kc][g][0], Br[kc][g][1]);
            }
        }

        // shadow work 3: stage x(t+2); prefetch x(t+3)
        if (t + 2 < TT) {
            L1_STAGE(Asm + (t & 1) * 768);
            if (t + 3 < TT) {
                const int tt3 = dir ? tt - 3 : tt + 3;
                v0 = *(const float4*)(xL0 + (size_t)tt3 * 64);
                v1 = *(const float4*)(xL1 + (size_t)tt3 * 64);
            }
        }

        __syncthreads();
    }

    {
        const int tlast = dir ? 0 : TT - 1;
        const uint2 hv = *(const uint2*)&houtS[((TT - 1) & 1) * 288 + sF * 18 + ocF * 2];
        *(uint2*)&g_h1b[((size_t)(ws + sF) * TT + tlast) * 32 + dir * 16 + ocF * 2] = hv;
    }
}

// ================= layer 2: H=16, K=80 (KC=5), last-h only ===================
// R11 skeleton + RECURRENCE SPLIT: h-part is a single kc (kc4); x-part kc0-3
// pre-accumulated in the shadow. One __syncthreads/step.
__global__ void __launch_bounds__(64) lstm2_mma(
    const float* __restrict__ W2f, const float* __restrict__ U2f, const float* __restrict__ b2f,
    const float* __restrict__ W2b, const float* __restrict__ U2b, const float* __restrict__ b2b)
{
    __shared__ uint32_t Bsm[5 * 8 * 32 * 2];               // 10KB (init only)
    __shared__ __align__(16) uint32_t Asm[2 * 5 * 128];    // 5KB, 2 buffers
    __shared__ float biasS[64];

    const int dir = blockIdx.y;
    const float* W    = dir ? W2b : W2f;
    const float* U    = dir ? U2b : U2f;
    const float* bias = dir ? b2b : b2f;

    const int tid  = threadIdx.x;
    const int half = tid >> 5;
    const int l    = tid & 31;
    const int gid  = l >> 2;
    const int tig  = l & 3;

    for (int idx = tid; idx < 5 * 8 * 32 * 2; idx += 64) {
        const int which = idx & 1;
        const int lane  = (idx >> 1) & 31;
        const int nt    = (idx >> 6) & 7;
        const int kc    = idx >> 9;
        const int k = kc * 16 + which * 8 + 2 * (lane & 3);
        const int n = nt * 8 + (lane >> 2);
        const float v0w = (k     < 64) ? W[k * 64 + n]       : U[(k - 64) * 64 + n];
        const float v1w = (k + 1 < 64) ? W[(k + 1) * 64 + n] : U[(k - 63) * 64 + n];
        Bsm[idx] = bf2(v0w, v1w);
    }
    if (tid < 64) biasS[tid] = bias[tid];
    for (int idx = tid; idx < 128; idx += 64) Asm[4 * 128 + idx] = 0;  // hbuf buf0
    __syncthreads();

    uint32_t Br[5][4][2];
    #pragma unroll
    for (int kc = 0; kc < 5; kc++)
        #pragma unroll
        for (int g = 0; g < 4; g++) {
            const int base = ((kc * 8 + g * 2 + half) * 32 + l) * 2;
            Br[kc][g][0] = Bsm[base];
            Br[kc][g][1] = Bsm[base + 1];
        }

    float2 bz[4];
    #pragma unroll
    for (int g = 0; g < 4; g++) {
        const int col = g * 16 + half * 8 + 2 * tig;
        bz[g] = make_float2(biasS[col], biasS[col + 1]);
    }

    const int ws = blockIdx.x * 16;

    const int kcS  = tid >> 4;
    const int gidS = (tid & 15) >> 1;
    const int tp   = tid & 1;
    const int j0   = gidS * 4 + 2 * tp;
    const uint32_t* h0p = g_h1b + (size_t)(ws + gidS) * TT * 32 + kcS * 8 + 2 * tp;
    const uint32_t* h1p = h0p + (size_t)8 * TT * 32;

    float cc[4] = {0.f, 0.f, 0.f, 0.f};
    float d[4][4];   // loop-carried
    uint2 lo0, lo1, hi0, hi1;

#define L2_LOAD(TTI) do { \
    lo0 = *(const uint2*)(h0p + (size_t)(TTI) * 32); \
    lo1 = *(const uint2*)(h1p + (size_t)(TTI) * 32); \
    hi0 = *(const uint2*)(h0p + (size_t)(TTI) * 32 + 4); \
    hi1 = *(const uint2*)(h1p + (size_t)(TTI) * 32 + 4); \
} while (0)
#define L2_STAGE(DST) do { \
    *(uint4*)((DST) + kcS * 128 + j0 * 4)       = make_uint4(lo0.x, lo1.x, hi0.x, hi1.x); \
    *(uint4*)((DST) + kcS * 128 + (j0 + 1) * 4) = make_uint4(lo0.y, lo1.y, hi0.y, hi1.y); \
} while (0)

    // ---- prologue ----
    L2_LOAD(dir ? TT - 1 : 0);
    L2_STAGE(Asm);
    __syncthreads();
    #pragma unroll
    for (int g = 0; g < 4; g++) {
        d[g][0] = bz[g].x; d[g][1] = bz[g].y;
        d[g][2] = bz[g].x; d[g][3] = bz[g].y;
    }
    #pragma unroll
    for (int kc = 0; kc < 4; kc++) {
        const uint4 a = *((const uint4*)Asm + kc * 32 + l);
        #pragma unroll
        for (int g = 0; g < 4; g++)
            mma_bf16(d[g], a, Br[kc][g][0], Br[kc][g][1]);
    }
    L2_LOAD(dir ? TT - 2 : 1);
    L2_STAGE(Asm + 640);
    L2_LOAD(dir ? TT - 3 : 2);
    __syncthreads();

    for (int t = 0; t < TT; t++) {
        const int tt = dir ? TT - 1 - t : t;
        const uint32_t* Acur = Asm + (t & 1) * 640;
        uint32_t*       Anxt = Asm + ((t + 1) & 1) * 640;

        // ---- critical path: single h-part MMA (kc4) ----
        {
            const uint4 a = *((const uint4*)Acur + 4 * 32 + l);
            #pragma unroll
            for (int g = 0; g < 4; g++)
                mma_bf16(d[g], a, Br[4][g][0], Br[4][g][1]);
        }

        // ---- activations ----
        uint32_t hp[2];
        float hlast[4];
        #pragma unroll
        for (int rh = 0; rh < 2; rh++) {
            float h0, h1;
            {
                const int p = rh * 2;
                const float ig = sigx(d[0][p]);
                const float fg = sigx(d[1][p]);
                const float gg = tanhx(d[2][p]);
                const float og = sigx(d[3][p]);
                const float c  = fg * cc[p] + ig * gg;
                h0 = og * tanhx(c); cc[p] = c;
            }
            {
                const int p = rh * 2 + 1;
                const float ig = sigx(d[0][p]);
                const float fg = sigx(d[1][p]);
                const float gg = tanhx(d[2][p]);
                const float og = sigx(d[3][p]);
                const float c  = fg * cc[p] + ig * gg;
                h1 = og * tanhx(c); cc[p] = c;
            }
            hp[rh] = bf2(h0, h1);
            hlast[rh * 2] = h0; hlast[rh * 2 + 1] = h1;
        }
        *(uint2*)(Anxt + 4 * 128 + l * 4 + half * 2) = make_uint2(hp[0], hp[1]);

        if (t == TT - 1) {
            #pragma unroll
            for (int rh = 0; rh < 2; rh++) {
                const int e0 = half * 8 + 2 * tig;
                *(float2*)&g_h2[(ws + gid + 8 * rh) * 32 + dir * 16 + e0]
                    = make_float2(hlast[rh * 2], hlast[rh * 2 + 1]);
            }
        }

        // shadow: pre-accumulate bias + x(t+1)@W
        if (t + 1 < TT) {
            #pragma unroll
            for (int g = 0; g < 4; g++) {
                d[g][0] = bz[g].x; d[g][1] = bz[g].y;
                d[g][2] = bz[g].x; d[g][3] = bz[g].y;
            }
            #pragma unroll
            for (int kc = 0; kc < 4; kc++) {
                const uint4 a = *((const uint4*)Anxt + kc * 32 + l);
                #pragma unroll
                for (int g = 0; g < 4; g++)
                    mma_bf16(d[g], a, Br[kc][g][0], Br[kc][g][1]);
            }
        }

        // shadow: stage x(t+2); prefetch x(t+3)
        if (t + 2 < TT) {
            L2_STAGE(Asm + (t & 1) * 640);
            if (t + 3 < TT) {
                const int tt3 = dir ? tt - 3 : tt + 3;
                L2_LOAD(tt3);
            }
        }

        __syncthreads();
    }
#undef L2_LOAD
#undef L2_STAGE
}

// ================= head: dense(8)+swish, dense(2)+sigmoid ================
__device__ __forceinline__ float sigf(float x) { return 1.0f / (1.0f + __expf(-x)); }

__global__ void head_kernel(
    const float* __restrict__ W3, const float* __restrict__ b3,
    const float* __restrict__ W4, const float* __restrict__ b4,
    float* __restrict__ out, int B)
{
    const int b = blockIdx.x * blockDim.x + threadIdx.x;
    if (b >= B) return;

    float xvv[32];
    #pragma unroll
    for (int i = 0; i < 32; i++) xvv[i] = g_h2[b * 32 + i];

    float y[8];
    #pragma unroll
    for (int o = 0; o < 8; o++) {
        float acc = b3[o];
        #pragma unroll
        for (int k = 0; k < 32; k++)
            acc = fmaf(xvv[k], W3[k * 8 + o], acc);
        y[o] = acc * sigf(acc);
    }

    #pragma unroll
    for (int m = 0; m < 2; m++) {
        float acc = b4[m];
        #pragma unroll
        for (int o = 0; o < 8; o++)
            acc = fmaf(y[o], W4[o * 2 + m], acc);
        out[b * 2 + m] = sigf(acc);
    }
}

// ================= launch ================
extern "C" void kernel_launch(void* const* d_in, const int* in_sizes, int n_in,
                              void* d_out, int out_size)
{
    const float* x   = (const float*)d_in[0];
    const float* W1f = (const float*)d_in[1];
    const float* U1f = (const float*)d_in[2];
    const float* b1f = (const float*)d_in[3];
    const float* W1b = (const float*)d_in[4];
    const float* U1b = (const float*)d_in[5];
    const float* b1b = (const float*)d_in[6];
    const float* W2f = (const float*)d_in[7];
    const float* U2f = (const float*)d_in[8];
    const float* b2f = (const float*)d_in[9];
    const float* W2b = (const float*)d_in[10];
    const float* U2b = (const float*)d_in[11];
    const float* b2b = (const float*)d_in[12];
    const float* W3  = (const float*)d_in[13];
    const float* b3  = (const float*)d_in[14];
    const float* W4  = (const float*)d_in[15];
    const float* b4  = (const float*)d_in[16];
    float* out = (float*)d_out;

    const int B = in_sizes[0] / (TT * 64);   // 4096

    lstm1_mma<<<dim3(B / 16, 2), 128>>>(x, W1f, U1f, b1f, W1b, U1b, b1b);
    lstm2_mma<<<dim3(B / 16, 2), 64>>>(W2f, U2f, b2f, W2b, U2b, b2b);
    head_kernel<<<(B + 255) / 256, 256>>>(W3, b3, W4, b4, out, B);
}

// round 15
// speedup vs baseline: 1.1071x; 1.1071x over previous
#include <cuda_runtime.h>
#include <cuda_bf16.h>
#include <stdint.h>

#define TT 128
#define MAXB 4096

// ---------------- scratch ----------------
__device__ uint32_t g_h1b[(size_t)MAXB * TT * 32];  // layer1 bidi out, bf16x2 [B][T][32]
__device__ float    g_h2[MAXB * 32];                // layer2 concat [B][32]

// ---------------- helpers ----------------
__device__ __forceinline__ uint32_t bf2(float lo, float hi) {
    uint32_t r;
    asm("cvt.rn.bf16x2.f32 %0, %1, %2;" : "=r"(r) : "f"(hi), "f"(lo));
    return r;
}
__device__ __forceinline__ float tanhx(float x) {
    float y; asm("tanh.approx.f32 %0, %1;" : "=f"(y) : "f"(x)); return y;
}
__device__ __forceinline__ float sigx(float x) {
    return fmaf(tanhx(x * 0.5f), 0.5f, 0.5f);
}
__device__ __forceinline__ void mma_bf16(float* d, const uint4& a, uint32_t b0, uint32_t b1) {
    asm volatile(
        "mma.sync.aligned.m16n8k16.row.col.f32.bf16.bf16.f32 "
        "{%0,%1,%2,%3},{%4,%5,%6,%7},{%8,%9},{%0,%1,%2,%3};"
        : "+f"(d[0]), "+f"(d[1]), "+f"(d[2]), "+f"(d[3])
        : "r"(a.x), "r"(a.y), "r"(a.z), "r"(a.w), "r"(b0), "r"(b1));
}
// streaming loads (evict-first; read-once data)
__device__ __forceinline__ float4 ldcs4(const float* p) {
    float4 v;
    asm volatile("ld.global.cs.v4.f32 {%0,%1,%2,%3}, [%4];"
                 : "=f"(v.x), "=f"(v.y), "=f"(v.z), "=f"(v.w) : "l"(p));
    return v;
}
__device__ __forceinline__ uint2 ldcs2u(const uint32_t* p) {
    uint2 v;
    asm volatile("ld.global.cs.v2.u32 {%0,%1}, [%2];"
                 : "=r"(v.x), "=r"(v.y) : "l"(p));
    return v;
}

// ================= layer 1: H=32, KIN=64, K=96 (KC=6), seq out (bf16) ========
// R11 verbatim structure: 4-way N-split, B in regs, A double-buffered,
// 1 bar/step, wide x LDG.128(+cs) + shfl redistribution.
__global__ void __launch_bounds__(128) lstm1_mma(
    const float* __restrict__ in,
    const float* __restrict__ Wf, const float* __restrict__ Uf, const float* __restrict__ bf_,
    const float* __restrict__ Wb, const float* __restrict__ Ub, const float* __restrict__ bb)
{
    __shared__ uint32_t Bsm[6 * 16 * 32 * 2];               // 24KB (init only)
    __shared__ __align__(16) uint32_t Asm[2 * 6 * 32 * 4];  // 6KB, 2 buffers
    __shared__ __align__(16) uint32_t houtS[2 * 16 * 18];   // 2.25KB, 2 buffers
    __shared__ float biasS[128];

    const int dir = blockIdx.y;
    const float* W    = dir ? Wb : Wf;
    const float* U    = dir ? Ub : Uf;
    const float* bias = dir ? bb : bf_;

    const int tid = threadIdx.x;
    const int q   = tid >> 5;
    const int l   = tid & 31;
    const int gid = l >> 2;
    const int tig = l & 3;

    for (int idx = tid; idx < 6 * 16 * 32 * 2; idx += 128) {
        const int which = idx & 1;
        const int lane  = (idx >> 1) & 31;
        const int nt    = (idx >> 6) & 15;
        const int kc    = idx >> 10;
        const int k = kc * 16 + which * 8 + 2 * (lane & 3);
        const int n = nt * 8 + (lane >> 2);
        const float v0w = (k     < 64) ? W[k * 128 + n]       : U[(k - 64) * 128 + n];
        const float v1w = (k + 1 < 64) ? W[(k + 1) * 128 + n] : U[(k - 63) * 128 + n];
        Bsm[idx] = bf2(v0w, v1w);
    }
    if (tid < 128) biasS[tid] = bias[tid];
    for (int idx = tid; idx < 256; idx += 128) Asm[512 + idx] = 0;
    __syncthreads();

    uint32_t Br[6][4][2];
    #pragma unroll
    for (int kc = 0; kc < 6; kc++)
        #pragma unroll
        for (int g = 0; g < 4; g++) {
            const int base = ((kc * 16 + g * 4 + q) * 32 + l) * 2;
            Br[kc][g][0] = Bsm[base];
            Br[kc][g][1] = Bsm[base + 1];
        }

    float2 bz[4];
    #pragma unroll
    for (int g = 0; g < 4; g++) {
        const int col = g * 32 + q * 8 + 2 * tig;
        bz[g] = make_float2(biasS[col], biasS[col + 1]);
    }

    const int ws = blockIdx.x * 16;
    const float* xL0 = in + (size_t)(ws + gid) * TT * 64 + q * 16 + 4 * tig;
    const float* xL1 = xL0 + (size_t)8 * TT * 64;

    const int srcLo = (l & ~3) | (tig >> 1);
    const int srcHi = srcLo + 2;
    const bool oddT = (tig & 1) != 0;

    const int sF  = tid >> 3;
    const int ocF = tid & 7;

    float cc[4] = {0.f, 0.f, 0.f, 0.f};

    float4 v0, v1;

    {   // prologue: stage x_0 into buffer 0; prefetch x_1
        const int tt0 = dir ? TT - 1 : 0;
        v0 = ldcs4(xL0 + (size_t)tt0 * 64);
        v1 = ldcs4(xL1 + (size_t)tt0 * 64);
        const uint32_t pa0 = bf2(v0.x, v0.y), pa1 = bf2(v0.z, v0.w);
        const uint32_t pb0 = bf2(v1.x, v1.y), pb1 = bf2(v1.z, v1.w);
        const uint32_t a0l = __shfl_sync(0xffffffffu, pa0, srcLo);
        const uint32_t a1l = __shfl_sync(0xffffffffu, pa1, srcLo);
        const uint32_t b0l = __shfl_sync(0xffffffffu, pb0, srcLo);
        const uint32_t b1l = __shfl_sync(0xffffffffu, pb1, srcLo);
        const uint32_t a0h = __shfl_sync(0xffffffffu, pa0, srcHi);
        const uint32_t a1h = __shfl_sync(0xffffffffu, pa1, srcHi);
        const uint32_t b0h = __shfl_sync(0xffffffffu, pb0, srcHi);
        const uint32_t b1h = __shfl_sync(0xffffffffu, pb1, srcHi);
        *(uint4*)(Asm + q * 128 + l * 4) = make_uint4(
            oddT ? a1l : a0l, oddT ? b1l : b0l,
            oddT ? a1h : a0h, oddT ? b1h : b0h);
        if (TT > 1) {
            const int tt1 = dir ? TT - 2 : 1;
            v0 = ldcs4(xL0 + (size_t)tt1 * 64);
            v1 = ldcs4(xL1 + (size_t)tt1 * 64);
        }
    }
    __syncthreads();

    for (int t = 0; t < TT; t++) {
        const int tt = dir ? TT - 1 - t : t;
        const uint32_t* Acur = Asm + (t & 1) * 768;
        uint32_t*       Anxt = Asm + ((t + 1) & 1) * 768;

        // independent work first: flush hout(t-1) (reads houtS written pre-barrier)
        if (t > 0) {
            const int tprev = dir ? tt + 1 : tt - 1;
            const uint2 hv = *(const uint2*)&houtS[((t - 1) & 1) * 288 + sF * 18 + ocF * 2];
            *(uint2*)&g_h1b[((size_t)(ws + sF) * TT + tprev) * 32 + dir * 16 + ocF * 2] = hv;
        }

        float d[4][4];
        #pragma unroll
        for (int g = 0; g < 4; g++) {
            d[g][0] = bz[g].x; d[g][1] = bz[g].y;
            d[g][2] = bz[g].x; d[g][3] = bz[g].y;
        }
        #pragma unroll
        for (int kc = 0; kc < 6; kc++) {
            const uint4 a = *((const uint4*)Acur + kc * 32 + l);
            #pragma unroll
            for (int g = 0; g < 4; g++)
                mma_bf16(d[g], a, Br[kc][g][0], Br[kc][g][1]);
        }

        if (t + 1 < TT) {
            const uint32_t pa0 = bf2(v0.x, v0.y), pa1 = bf2(v0.z, v0.w);
            const uint32_t pb0 = bf2(v1.x, v1.y), pb1 = bf2(v1.z, v1.w);
            const uint32_t a0l = __shfl_sync(0xffffffffu, pa0, srcLo);
            const uint32_t a1l = __shfl_sync(0xffffffffu, pa1, srcLo);
            const uint32_t b0l = __shfl_sync(0xffffffffu, pb0, srcLo);
            const uint32_t b1l = __shfl_sync(0xffffffffu, pb1, srcLo);
            const uint32_t a0h = __shfl_sync(0xffffffffu, pa0, srcHi);
            const uint32_t a1h = __shfl_sync(0xffffffffu, pa1, srcHi);
            const uint32_t b0h = __shfl_sync(0xffffffffu, pb0, srcHi);
            const uint32_t b1h = __shfl_sync(0xffffffffu, pb1, srcHi);
            *(uint4*)(Anxt + q * 128 + l * 4) = make_uint4(
                oddT ? a1l : a0l, oddT ? b1l : b0l,
                oddT ? a1h : a0h, oddT ? b1h : b0h);
            if (t + 2 < TT) {
                const int tt2 = dir ? tt - 2 : tt + 2;
                v0 = ldcs4(xL0 + (size_t)tt2 * 64);
                v1 = ldcs4(xL1 + (size_t)tt2 * 64);
            }
        }

        uint32_t hp[2];
        #pragma unroll
        for (int rh = 0; rh < 2; rh++) {
            float h0, h1;
            {
                const int p = rh * 2;
                const float ig = sigx(d[0][p]);
                const float fg = sigx(d[1][p]);
                const float gg = tanhx(d[2][p]);
                const float og = sigx(d[3][p]);
                const float c  = fg * cc[p] + ig * gg;
                h0 = og * tanhx(c); cc[p] = c;
            }
            {
                const int p = rh * 2 + 1;
                const float ig = sigx(d[0][p]);
                const float fg = sigx(d[1][p]);
                const float gg = tanhx(d[2][p]);
                const float og = sigx(d[3][p]);
                const float c  = fg * cc[p] + ig * gg;
                h1 = og * tanhx(c); cc[p] = c;
            }
            hp[rh] = bf2(h0, h1);
            houtS[(t & 1) * 288 + (gid + 8 * rh) * 18 + q * 4 + tig] = hp[rh];
        }
        *(uint2*)(Anxt + (4 + (q >> 1)) * 128 + l * 4 + (q & 1) * 2)
            = make_uint2(hp[0], hp[1]);

        __syncthreads();
    }

    {
        const int tlast = dir ? 0 : TT - 1;
        const uint2 hv = *(const uint2*)&houtS[((TT - 1) & 1) * 288 + sF * 18 + ocF * 2];
        *(uint2*)&g_h1b[((size_t)(ws + sF) * TT + tlast) * 32 + dir * 16 + ocF * 2] = hv;
    }
}

// ================= layer 2: H=16, K=80 (KC=5), last-h only, M=16 =============
// R11 verbatim structure; g_h1b reads use streaming (evict-first) policy.
__global__ void __launch_bounds__(64) lstm2_mma(
    const float* __restrict__ W2f, const float* __restrict__ U2f, const float* __restrict__ b2f,
    const float* __restrict__ W2b, const float* __restrict__ U2b, const float* __restrict__ b2b)
{
    __shared__ uint32_t Bsm[5 * 8 * 32 * 2];               // 10KB (init only)
    __shared__ __align__(16) uint32_t Asm[2 * 5 * 128];    // 5KB, 2 buffers
    __shared__ float biasS[64];

    const int dir = blockIdx.y;
    const float* W    = dir ? W2b : W2f;
    const float* U    = dir ? U2b : U2f;
    const float* bias = dir ? b2b : b2f;

    const int tid  = threadIdx.x;
    const int half = tid >> 5;
    const int l    = tid & 31;
    const int gid  = l >> 2;
    const int tig  = l & 3;

    for (int idx = tid; idx < 5 * 8 * 32 * 2; idx += 64) {
        const int which = idx & 1;
        const int lane  = (idx >> 1) & 31;
        const int nt    = (idx >> 6) & 7;
        const int kc    = idx >> 9;
        const int k = kc * 16 + which * 8 + 2 * (lane & 3);
        const int n = nt * 8 + (lane >> 2);
        const float v0w = (k     < 64) ? W[k * 64 + n]       : U[(k - 64) * 64 + n];
        const float v1w = (k + 1 < 64) ? W[(k + 1) * 64 + n] : U[(k - 63) * 64 + n];
        Bsm[idx] = bf2(v0w, v1w);
    }
    if (tid < 64) biasS[tid] = bias[tid];
    for (int idx = tid; idx < 128; idx += 64) Asm[4 * 128 + idx] = 0;
    __syncthreads();

    uint32_t Br[5][4][2];
    #pragma unroll
    for (int kc = 0; kc < 5; kc++)
        #pragma unroll
        for (int g = 0; g < 4; g++) {
            const int base = ((kc * 8 + g * 2 + half) * 32 + l) * 2;
            Br[kc][g][0] = Bsm[base];
            Br[kc][g][1] = Bsm[base + 1];
        }

    float2 bz[4];
    #pragma unroll
    for (int g = 0; g < 4; g++) {
        const int col = g * 16 + half * 8 + 2 * tig;
        bz[g] = make_float2(biasS[col], biasS[col + 1]);
    }

    const int ws = blockIdx.x * 16;

    const int kcS  = tid >> 4;
    const int gidS = (tid & 15) >> 1;
    const int tp   = tid & 1;
    const int j0   = gidS * 4 + 2 * tp;
    const uint32_t* h0p = g_h1b + (size_t)(ws + gidS) * TT * 32 + kcS * 8 + 2 * tp;
    const uint32_t* h1p = h0p + (size_t)8 * TT * 32;

    float cc[4] = {0.f, 0.f, 0.f, 0.f};

    uint2 lo0, lo1, hi0, hi1;
    {
        const int tt0 = dir ? TT - 1 : 0;
        lo0 = ldcs2u(h0p + (size_t)tt0 * 32);
        lo1 = ldcs2u(h1p + (size_t)tt0 * 32);
        hi0 = ldcs2u(h0p + (size_t)tt0 * 32 + 4);
        hi1 = ldcs2u(h1p + (size_t)tt0 * 32 + 4);
        *(uint4*)(Asm + kcS * 128 + j0 * 4)       = make_uint4(lo0.x, lo1.x, hi0.x, hi1.x);
        *(uint4*)(Asm + kcS * 128 + (j0 + 1) * 4) = make_uint4(lo0.y, lo1.y, hi0.y, hi1.y);
        const int tt1 = dir ? TT - 2 : 1;
        lo0 = ldcs2u(h0p + (size_t)tt1 * 32);
        lo1 = ldcs2u(h1p + (size_t)tt1 * 32);
        hi0 = ldcs2u(h0p + (size_t)tt1 * 32 + 4);
        hi1 = ldcs2u(h1p + (size_t)tt1 * 32 + 4);
    }
    __syncthreads();

    for (int t = 0; t < TT; t++) {
        const int tt = dir ? TT - 1 - t : t;
        const uint32_t* Acur = Asm + (t & 1) * 640;
        uint32_t*       Anxt = Asm + ((t + 1) & 1) * 640;

        float d[4][4];
        #pragma unroll
        for (int g = 0; g < 4; g++) {
            d[g][0] = bz[g].x; d[g][1] = bz[g].y;
            d[g][2] = bz[g].x; d[g][3] = bz[g].y;
        }
        #pragma unroll
        for (int kc = 0; kc < 5; kc++) {
            const uint4 a = *((const uint4*)Acur + kc * 32 + l);
            #pragma unroll
            for (int g = 0; g < 4; g++)
                mma_bf16(d[g], a, Br[kc][g][0], Br[kc][g][1]);
        }

        if (t + 1 < TT) {
            *(uint4*)(Anxt + kcS * 128 + j0 * 4)       = make_uint4(lo0.x, lo1.x, hi0.x, hi1.x);
            *(uint4*)(Anxt + kcS * 128 + (j0 + 1) * 4) = make_uint4(lo0.y, lo1.y, hi0.y, hi1.y);
            if (t + 2 < TT) {
                const int tt2 = dir ? tt - 2 : tt + 2;
                lo0 = ldcs2u(h0p + (size_t)tt2 * 32);
                lo1 = ldcs2u(h1p + (size_t)tt2 * 32);
                hi0 = ldcs2u(h0p + (size_t)tt2 * 32 + 4);
                hi1 = ldcs2u(h1p + (size_t)tt2 * 32 + 4);
            }
        }

        uint32_t hp[2];
        float hlast[4];
        #pragma unroll
        for (int rh = 0; rh < 2; rh++) {
            float h0, h1;
            {
                const int p = rh * 2;
                const float ig = sigx(d[0][p]);
                const float fg = sigx(d[1][p]);
                const float gg = tanhx(d[2][p]);
                const float og = sigx(d[3][p]);
                const float c  = fg * cc[p] + ig * gg;
                h0 = og * tanhx(c); cc[p] = c;
            }
            {
                const int p = rh * 2 + 1;
                const float ig = sigx(d[0][p]);
                const float fg = sigx(d[1][p]);
                const float gg = tanhx(d[2][p]);
                const float og = sigx(d[3][p]);
                const float c  = fg * cc[p] + ig * gg;
                h1 = og * tanhx(c); cc[p] = c;
            }
            hp[rh] = bf2(h0, h1);
            hlast[rh * 2] = h0; hlast[rh * 2 + 1] = h1;
        }
        *(uint2*)(Anxt + 4 * 128 + l * 4 + half * 2) = make_uint2(hp[0], hp[1]);

        if (t == TT - 1) {
            #pragma unroll
            for (int rh = 0; rh < 2; rh++) {
                const int e0 = half * 8 + 2 * tig;
                *(float2*)&g_h2[(ws + gid + 8 * rh) * 32 + dir * 16 + e0]
                    = make_float2(hlast[rh * 2], hlast[rh * 2 + 1]);
            }
        }

        __syncthreads();
    }
}

// ================= head: dense(8)+swish, dense(2)+sigmoid ================
__device__ __forceinline__ float sigf(float x) { return 1.0f / (1.0f + __expf(-x)); }

__global__ void head_kernel(
    const float* __restrict__ W3, const float* __restrict__ b3,
    const float* __restrict__ W4, const float* __restrict__ b4,
    float* __restrict__ out, int B)
{
    const int b = blockIdx.x * blockDim.x + threadIdx.x;
    if (b >= B) return;

    float xvv[32];
    #pragma unroll
    for (int i = 0; i < 32; i++) xvv[i] = g_h2[b * 32 + i];

    float y[8];
    #pragma unroll
    for (int o = 0; o < 8; o++) {
        float acc = b3[o];
        #pragma unroll
        for (int k = 0; k < 32; k++)
            acc = fmaf(xvv[k], W3[k * 8 + o], acc);
        y[o] = acc * sigf(acc);
    }

    #pragma unroll
    for (int m = 0; m < 2; m++) {
        float acc = b4[m];
        #pragma unroll
        for (int o = 0; o < 8; o++)
            acc = fmaf(y[o], W4[o * 2 + m], acc);
        out[b * 2 + m] = sigf(acc);
    }
}

// ================= launch ================
extern "C" void kernel_launch(void* const* d_in, const int* in_sizes, int n_in,
                              void* d_out, int out_size)
{
    const float* x   = (const float*)d_in[0];
    const float* W1f = (const float*)d_in[1];
    const float* U1f = (const float*)d_in[2];
    const float* b1f = (const float*)d_in[3];
    const float* W1b = (const float*)d_in[4];
    const float* U1b = (const float*)d_in[5];
    const float* b1b = (const float*)d_in[6];
    const float* W2f = (const float*)d_in[7];
    const float* U2f = (const float*)d_in[8];
    const float* b2f = (const float*)d_in[9];
    const float* W2b = (const float*)d_in[10];
    const float* U2b = (const float*)d_in[11];
    const float* b2b = (const float*)d_in[12];
    const float* W3  = (const float*)d_in[13];
    const float* b3  = (const float*)d_in[14];
    const float* W4  = (const float*)d_in[15];
    const float* b4  = (const float*)d_in[16];
    float* out = (float*)d_out;

    const int B = in_sizes[0] / (TT * 64);   // 4096

    lstm1_mma<<<dim3(B / 16, 2), 128>>>(x, W1f, U1f, b1f, W1b, U1b, b1b);
    lstm2_mma<<<dim3(B / 16, 2), 64>>>(W2f, U2f, b2f, W2b, U2b, b2b);
    head_kernel<<<(B + 255) / 256, 256>>>(W3, b3, W4, b4, out, B);
}

// round 16
// speedup vs baseline: 1.2172x; 1.0995x over previous
#include <cuda_runtime.h>
#include <cuda_bf16.h>
#include <stdint.h>

#define TT 128
#define MAXB 4096

// ---------------- scratch ----------------
// layer1 output stored DIRECTLY in lstm2's A-fragment layout:
// [group(B/16)][t][kc(4)][128 u32]; kc0-1 = fwd h, kc2-3 = bwd h.
__device__ uint32_t g_h1frag[(size_t)(MAXB / 16) * TT * 4 * 128];
__device__ float    g_h2[MAXB * 32];                // layer2 concat [B][32]

// ---------------- helpers ----------------
__device__ __forceinline__ uint32_t bf2(float lo, float hi) {
    uint32_t r;
    asm("cvt.rn.bf16x2.f32 %0, %1, %2;" : "=r"(r) : "f"(hi), "f"(lo));
    return r;
}
__device__ __forceinline__ float tanhx(float x) {
    float y; asm("tanh.approx.f32 %0, %1;" : "=f"(y) : "f"(x)); return y;
}
__device__ __forceinline__ float sigx(float x) {
    return fmaf(tanhx(x * 0.5f), 0.5f, 0.5f);
}
__device__ __forceinline__ void mma_bf16(float* d, const uint4& a, uint32_t b0, uint32_t b1) {
    asm volatile(
        "mma.sync.aligned.m16n8k16.row.col.f32.bf16.bf16.f32 "
        "{%0,%1,%2,%3},{%4,%5,%6,%7},{%8,%9},{%0,%1,%2,%3};"
        : "+f"(d[0]), "+f"(d[1]), "+f"(d[2]), "+f"(d[3])
        : "r"(a.x), "r"(a.y), "r"(a.z), "r"(a.w), "r"(b0), "r"(b1));
}
// streaming loads (evict-first; read-once data)
__device__ __forceinline__ float4 ldcs4(const float* p) {
    float4 v;
    asm volatile("ld.global.cs.v4.f32 {%0,%1,%2,%3}, [%4];"
                 : "=f"(v.x), "=f"(v.y), "=f"(v.z), "=f"(v.w) : "l"(p));
    return v;
}
__device__ __forceinline__ uint4 ldcs4u(const uint4* p) {
    uint4 v;
    asm volatile("ld.global.cs.v4.u32 {%0,%1,%2,%3}, [%4];"
                 : "=r"(v.x), "=r"(v.y), "=r"(v.z), "=r"(v.w) : "l"(p));
    return v;
}

// ================= layer 1: H=32, KIN=64, K=96 (KC=6), frag-out ==============
// R15 skeleton (4-way N-split, B regs, A double-buffered, 1 bar/step, cs x
// loads + shfl). hout path REPLACED by a single direct st.global.v2 per thread
// per step into g_h1frag (lstm2 A-fragment layout). No houtS smem.
__global__ void __launch_bounds__(128) lstm1_mma(
    const float* __restrict__ in,
    const float* __restrict__ Wf, const float* __restrict__ Uf, const float* __restrict__ bf_,
    const float* __restrict__ Wb, const float* __restrict__ Ub, const float* __restrict__ bb)
{
    __shared__ uint32_t Bsm[6 * 16 * 32 * 2];               // 24KB (init only)
    __shared__ __align__(16) uint32_t Asm[2 * 6 * 32 * 4];  // 6KB, 2 buffers
    __shared__ float biasS[128];

    const int dir = blockIdx.y;
    const float* W    = dir ? Wb : Wf;
    const float* U    = dir ? Ub : Uf;
    const float* bias = dir ? bb : bf_;

    const int tid = threadIdx.x;
    const int q   = tid >> 5;
    const int l   = tid & 31;
    const int gid = l >> 2;
    const int tig = l & 3;

    for (int idx = tid; idx < 6 * 16 * 32 * 2; idx += 128) {
        const int which = idx & 1;
        const int lane  = (idx >> 1) & 31;
        const int nt    = (idx >> 6) & 15;
        const int kc    = idx >> 10;
        const int k = kc * 16 + which * 8 + 2 * (lane & 3);
        const int n = nt * 8 + (lane >> 2);
        const float v0w = (k     < 64) ? W[k * 128 + n]       : U[(k - 64) * 128 + n];
        const float v1w = (k + 1 < 64) ? W[(k + 1) * 128 + n] : U[(k - 63) * 128 + n];
        Bsm[idx] = bf2(v0w, v1w);
    }
    if (tid < 128) biasS[tid] = bias[tid];
    for (int idx = tid; idx < 256; idx += 128) Asm[512 + idx] = 0;
    __syncthreads();

    uint32_t Br[6][4][2];
    #pragma unroll
    for (int kc = 0; kc < 6; kc++)
        #pragma unroll
        for (int g = 0; g < 4; g++) {
            const int base = ((kc * 16 + g * 4 + q) * 32 + l) * 2;
            Br[kc][g][0] = Bsm[base];
            Br[kc][g][1] = Bsm[base + 1];
        }

    float2 bz[4];
    #pragma unroll
    for (int g = 0; g < 4; g++) {
        const int col = g * 32 + q * 8 + 2 * tig;
        bz[g] = make_float2(biasS[col], biasS[col + 1]);
    }

    const int ws = blockIdx.x * 16;
    const float* xL0 = in + (size_t)(ws + gid) * TT * 64 + q * 16 + 4 * tig;
    const float* xL1 = xL0 + (size_t)8 * TT * 64;

    const int srcLo = (l & ~3) | (tig >> 1);
    const int srcHi = srcLo + 2;
    const bool oddT = (tig & 1) != 0;

    // direct fragment-output pointer pieces:
    // u32 index = ((group*TT + tt)*4 + kcOut)*128 + l*4 + (q&1)*2
    const int kcOut = dir * 2 + (q >> 1);
    uint32_t* fragBase = g_h1frag + ((size_t)blockIdx.x * TT * 4 + kcOut) * 128
                         + l * 4 + (q & 1) * 2;

    float cc[4] = {0.f, 0.f, 0.f, 0.f};

    float4 v0, v1;

    {   // prologue: stage x_0 into buffer 0; prefetch x_1
        const int tt0 = dir ? TT - 1 : 0;
        v0 = ldcs4(xL0 + (size_t)tt0 * 64);
        v1 = ldcs4(xL1 + (size_t)tt0 * 64);
        const uint32_t pa0 = bf2(v0.x, v0.y), pa1 = bf2(v0.z, v0.w);
        const uint32_t pb0 = bf2(v1.x, v1.y), pb1 = bf2(v1.z, v1.w);
        const uint32_t a0l = __shfl_sync(0xffffffffu, pa0, srcLo);
        const uint32_t a1l = __shfl_sync(0xffffffffu, pa1, srcLo);
        const uint32_t b0l = __shfl_sync(0xffffffffu, pb0, srcLo);
        const uint32_t b1l = __shfl_sync(0xffffffffu, pb1, srcLo);
        const uint32_t a0h = __shfl_sync(0xffffffffu, pa0, srcHi);
        const uint32_t a1h = __shfl_sync(0xffffffffu, pa1, srcHi);
        const uint32_t b0h = __shfl_sync(0xffffffffu, pb0, srcHi);
        const uint32_t b1h = __shfl_sync(0xffffffffu, pb1, srcHi);
        *(uint4*)(Asm + q * 128 + l * 4) = make_uint4(
            oddT ? a1l : a0l, oddT ? b1l : b0l,
            oddT ? a1h : a0h, oddT ? b1h : b0h);
        if (TT > 1) {
            const int tt1 = dir ? TT - 2 : 1;
            v0 = ldcs4(xL0 + (size_t)tt1 * 64);
            v1 = ldcs4(xL1 + (size_t)tt1 * 64);
        }
    }
    __syncthreads();

    for (int t = 0; t < TT; t++) {
        const int tt = dir ? TT - 1 - t : t;
        const uint32_t* Acur = Asm + (t & 1) * 768;
        uint32_t*       Anxt = Asm + ((t + 1) & 1) * 768;

        float d[4][4];
        #pragma unroll
        for (int g = 0; g < 4; g++) {
            d[g][0] = bz[g].x; d[g][1] = bz[g].y;
            d[g][2] = bz[g].x; d[g][3] = bz[g].y;
        }
        #pragma unroll
        for (int kc = 0; kc < 6; kc++) {
            const uint4 a = *((const uint4*)Acur + kc * 32 + l);
            #pragma unroll
            for (int g = 0; g < 4; g++)
                mma_bf16(d[g], a, Br[kc][g][0], Br[kc][g][1]);
        }

        if (t + 1 < TT) {
            const uint32_t pa0 = bf2(v0.x, v0.y), pa1 = bf2(v0.z, v0.w);
            const uint32_t pb0 = bf2(v1.x, v1.y), pb1 = bf2(v1.z, v1.w);
            const uint32_t a0l = __shfl_sync(0xffffffffu, pa0, srcLo);
            const uint32_t a1l = __shfl_sync(0xffffffffu, pa1, srcLo);
            const uint32_t b0l = __shfl_sync(0xffffffffu, pb0, srcLo);
            const uint32_t b1l = __shfl_sync(0xffffffffu, pb1, srcLo);
            const uint32_t a0h = __shfl_sync(0xffffffffu, pa0, srcHi);
            const uint32_t a1h = __shfl_sync(0xffffffffu, pa1, srcHi);
            const uint32_t b0h = __shfl_sync(0xffffffffu, pb0, srcHi);
            const uint32_t b1h = __shfl_sync(0xffffffffu, pb1, srcHi);
            *(uint4*)(Anxt + q * 128 + l * 4) = make_uint4(
                oddT ? a1l : a0l, oddT ? b1l : b0l,
                oddT ? a1h : a0h, oddT ? b1h : b0h);
            if (t + 2 < TT) {
                const int tt2 = dir ? tt - 2 : tt + 2;
                v0 = ldcs4(xL0 + (size_t)tt2 * 64);
                v1 = ldcs4(xL1 + (size_t)tt2 * 64);
            }
        }

        uint32_t hp[2];
        #pragma unroll
        for (int rh = 0; rh < 2; rh++) {
            float h0, h1;
            {
                const int p = rh * 2;
                const float ig = sigx(d[0][p]);
                const float fg = sigx(d[1][p]);
                const float gg = tanhx(d[2][p]);
                const float og = sigx(d[3][p]);
                const float c  = fg * cc[p] + ig * gg;
                h0 = og * tanhx(c); cc[p] = c;
            }
            {
                const int p = rh * 2 + 1;
                const float ig = sigx(d[0][p]);
                const float fg = sigx(d[1][p]);
                const float gg = tanhx(d[2][p]);
                const float og = sigx(d[3][p]);
                const float c  = fg * cc[p] + ig * gg;
                h1 = og * tanhx(c); cc[p] = c;
            }
            hp[rh] = bf2(h0, h1);
        }
        // h feedback (smem) + direct fragment store (gmem)
        *(uint2*)(Anxt + (4 + (q >> 1)) * 128 + l * 4 + (q & 1) * 2)
            = make_uint2(hp[0], hp[1]);
        *(uint2*)(fragBase + (size_t)tt * 512) = make_uint2(hp[0], hp[1]);

        __syncthreads();
    }
}

// ================= layer 2: H=16, K=80 (KC=5), last-h only ===================
// R15 skeleton; staging now PURE COPY: ld.global.cs.v4 from g_h1frag (already
// in A-fragment layout) -> STS.128. No swizzle math.
__global__ void __launch_bounds__(64) lstm2_mma(
    const float* __restrict__ W2f, const float* __restrict__ U2f, const float* __restrict__ b2f,
    const float* __restrict__ W2b, const float* __restrict__ U2b, const float* __restrict__ b2b)
{
    __shared__ uint32_t Bsm[5 * 8 * 32 * 2];               // 10KB (init only)
    __shared__ __align__(16) uint32_t Asm[2 * 5 * 128];    // 5KB, 2 buffers
    __shared__ float biasS[64];

    const int dir = blockIdx.y;
    const float* W    = dir ? W2b : W2f;
    const float* U    = dir ? U2b : U2f;
    const float* bias = dir ? b2b : b2f;

    const int tid  = threadIdx.x;
    const int half = tid >> 5;
    const int l    = tid & 31;
    const int gid  = l >> 2;
    const int tig  = l & 3;

    for (int idx = tid; idx < 5 * 8 * 32 * 2; idx += 64) {
        const int which = idx & 1;
        const int lane  = (idx >> 1) & 31;
        const int nt    = (idx >> 6) & 7;
        const int kc    = idx >> 9;
        const int k = kc * 16 + which * 8 + 2 * (lane & 3);
        const int n = nt * 8 + (lane >> 2);
        const float v0w = (k     < 64) ? W[k * 64 + n]       : U[(k - 64) * 64 + n];
        const float v1w = (k + 1 < 64) ? W[(k + 1) * 64 + n] : U[(k - 63) * 64 + n];
        Bsm[idx] = bf2(v0w, v1w);
    }
    if (tid < 64) biasS[tid] = bias[tid];
    for (int idx = tid; idx < 128; idx += 64) Asm[4 * 128 + idx] = 0;
    __syncthreads();

    uint32_t Br[5][4][2];
    #pragma unroll
    for (int kc = 0; kc < 5; kc++)
        #pragma unroll
        for (int g = 0; g < 4; g++) {
            const int base = ((kc * 8 + g * 2 + half) * 32 + l) * 2;
            Br[kc][g][0] = Bsm[base];
            Br[kc][g][1] = Bsm[base + 1];
        }

    float2 bz[4];
    #pragma unroll
    for (int g = 0; g < 4; g++) {
        const int col = g * 16 + half * 8 + 2 * tig;
        bz[g] = make_float2(biasS[col], biasS[col + 1]);
    }

    const int ws = blockIdx.x * 16;

    // staging: thread tid (0-63) -> kcS (0-3), lanes lnS and lnS+16
    const int kcS = tid >> 4;
    const int lnS = tid & 15;
    const uint4* srcBase = (const uint4*)g_h1frag + (size_t)blockIdx.x * TT * 128
                           + kcS * 32;   // per t: 4 kc * 32 uint4 = 128

    float cc[4] = {0.f, 0.f, 0.f, 0.f};

    uint4 pa, pb;
#define L2_LOAD(TTI) do { \
    const uint4* s = srcBase + (size_t)(TTI) * 128; \
    pa = ldcs4u(s + lnS); \
    pb = ldcs4u(s + lnS + 16); \
} while (0)
#define L2_STAGE(DST) do { \
    *(uint4*)((DST) + kcS * 128 + lnS * 4)        = pa; \
    *(uint4*)((DST) + kcS * 128 + (lnS + 16) * 4) = pb; \
} while (0)

    {   // prologue
        const int tt0 = dir ? TT - 1 : 0;
        L2_LOAD(tt0);
        L2_STAGE(Asm);
        const int tt1 = dir ? TT - 2 : 1;
        L2_LOAD(tt1);
    }
    __syncthreads();

    for (int t = 0; t < TT; t++) {
        const int tt = dir ? TT - 1 - t : t;
        const uint32_t* Acur = Asm + (t & 1) * 640;
        uint32_t*       Anxt = Asm + ((t + 1) & 1) * 640;

        float d[4][4];
        #pragma unroll
        for (int g = 0; g < 4; g++) {
            d[g][0] = bz[g].x; d[g][1] = bz[g].y;
            d[g][2] = bz[g].x; d[g][3] = bz[g].y;
        }
        #pragma unroll
        for (int kc = 0; kc < 5; kc++) {
            const uint4 a = *((const uint4*)Acur + kc * 32 + l);
            #pragma unroll
            for (int g = 0; g < 4; g++)
                mma_bf16(d[g], a, Br[kc][g][0], Br[kc][g][1]);
        }

        if (t + 1 < TT) {
            L2_STAGE(Anxt);
            if (t + 2 < TT) {
                const int tt2 = dir ? tt - 2 : tt + 2;
                L2_LOAD(tt2);
            }
        }

        uint32_t hp[2];
        float hlast[4];
        #pragma unroll
        for (int rh = 0; rh < 2; rh++) {
            float h0, h1;
            {
                const int p = rh * 2;
                const float ig = sigx(d[0][p]);
                const float fg = sigx(d[1][p]);
                const float gg = tanhx(d[2][p]);
                const float og = sigx(d[3][p]);
                const float c  = fg * cc[p] + ig * gg;
                h0 = og * tanhx(c); cc[p] = c;
            }
            {
                const int p = rh * 2 + 1;
                const float ig = sigx(d[0][p]);
                const float fg = sigx(d[1][p]);
                const float gg = tanhx(d[2][p]);
                const float og = sigx(d[3][p]);
                const float c  = fg * cc[p] + ig * gg;
                h1 = og * tanhx(c); cc[p] = c;
            }
            hp[rh] = bf2(h0, h1);
            hlast[rh * 2] = h0; hlast[rh * 2 + 1] = h1;
        }
        *(uint2*)(Anxt + 4 * 128 + l * 4 + half * 2) = make_uint2(hp[0], hp[1]);

        if (t == TT - 1) {
            #pragma unroll
            for (int rh = 0; rh < 2; rh++) {
                const int e0 = half * 8 + 2 * tig;
                *(float2*)&g_h2[(ws + gid + 8 * rh) * 32 + dir * 16 + e0]
                    = make_float2(hlast[rh * 2], hlast[rh * 2 + 1]);
            }
        }

        __syncthreads();
    }
#undef L2_LOAD
#undef L2_STAGE
}

// ================= head: dense(8)+swish, dense(2)+sigmoid ================
__device__ __forceinline__ float sigf(float x) { return 1.0f / (1.0f + __expf(-x)); }

__global__ void head_kernel(
    const float* __restrict__ W3, const float* __restrict__ b3,
    const float* __restrict__ W4, const float* __restrict__ b4,
    float* __restrict__ out, int B)
{
    const int b = blockIdx.x * blockDim.x + threadIdx.x;
    if (b >= B) return;

    float xvv[32];
    #pragma unroll
    for (int i = 0; i < 32; i++) xvv[i] = g_h2[b * 32 + i];

    float y[8];
    #pragma unroll
    for (int o = 0; o < 8; o++) {
        float acc = b3[o];
        #pragma unroll
        for (int k = 0; k < 32; k++)
            acc = fmaf(xvv[k], W3[k * 8 + o], acc);
        y[o] = acc * sigf(acc);
    }

    #pragma unroll
    for (int m = 0; m < 2; m++) {
        float acc = b4[m];
        #pragma unroll
        for (int o = 0; o < 8; o++)
            acc = fmaf(y[o], W4[o * 2 + m], acc);
        out[b * 2 + m] = sigf(acc);
    }
}

// ================= launch ================
extern "C" void kernel_launch(void* const* d_in, const int* in_sizes, int n_in,
                              void* d_out, int out_size)
{
    const float* x   = (const float*)d_in[0];
    const float* W1f = (const float*)d_in[1];
    const float* U1f = (const float*)d_in[2];
    const float* b1f = (const float*)d_in[3];
    const float* W1b = (const float*)d_in[4];
    const float* U1b = (const float*)d_in[5];
    const float* b1b = (const float*)d_in[6];
    const float* W2f = (const float*)d_in[7];
    const float* U2f = (const float*)d_in[8];
    const float* b2f = (const float*)d_in[9];
    const float* W2b = (const float*)d_in[10];
    const float* U2b = (const float*)d_in[11];
    const float* b2b = (const float*)d_in[12];
    const float* W3  = (const float*)d_in[13];
    const float* b3  = (const float*)d_in[14];
    const float* W4  = (const float*)d_in[15];
    const float* b4  = (const float*)d_in[16];
    float* out = (float*)d_out;

    const int B = in_sizes[0] / (TT * 64);   // 4096

    lstm1_mma<<<dim3(B / 16, 2), 128>>>(x, W1f, U1f, b1f, W1b, U1b, b1b);
    lstm2_mma<<<dim3(B / 16, 2), 64>>>(W2f, U2f, b2f, W2b, U2b, b2b);
    head_kernel<<<(B + 255) / 256, 256>>>(W3, b3, W4, b4, out, B);
}